// round 10
// baseline (speedup 1.0000x reference)
#include <cuda_runtime.h>
#include <cuda_bf16.h>
#include <cuda_fp16.h>
#include <cstdint>

#define N_NODES 100000
#define N_EDGES 1600000
#define HID 128
#define NGRAPH 64
#define NCLASS 10
#define SCAN_NB ((N_NODES + 1023) / 1024)
#define NTILES128 ((N_NODES + 127) / 128)
#define PROJ_GRID 148

// ---------------- scratch (no allocations allowed) ----------------
__device__ uint4  g_Z1[N_NODES * 16];     // h@Wl^T, fp16 (ping)
__device__ uint4  g_Y1[N_NODES * 16];     // h@Wr^T + b, fp16 (ping)
__device__ uint4  g_Z2[N_NODES * 16];     // pong
__device__ uint4  g_Y2[N_NODES * 16];     // pong
__device__ __half g_h3[N_NODES * HID];    // final layer output, fp16
__device__ uint4  g_Bh[3 * 4096];         // per-layer [Wl;Wr] bf16 hi
__device__ uint4  g_Bl[3 * 4096];         // per-layer lo
__device__ int    g_cnt[N_NODES];
__device__ int    g_off[N_NODES + 1];
__device__ int    g_ssrc[N_EDGES];
__device__ int    g_bsum[1024];
__device__ float  g_pool[NGRAPH * HID];

// ---------------- CSR build ----------------
__global__ void k_init() {
    int i = blockIdx.x * blockDim.x + threadIdx.x;
    if (i < N_NODES) g_cnt[i] = 0;
    if (i < NGRAPH * HID) g_pool[i] = 0.0f;
}
__global__ void k_hist(const int* __restrict__ dst) {
    int e = blockIdx.x * blockDim.x + threadIdx.x;
    if (e < N_EDGES) atomicAdd(&g_cnt[dst[e]], 1);
}
__global__ void k_scan1() {
    __shared__ int sh[1024];
    int t = threadIdx.x;
    int i = blockIdx.x * 1024 + t;
    int v = (i < N_NODES) ? g_cnt[i] : 0;
    sh[t] = v;
    __syncthreads();
    for (int d = 1; d < 1024; d <<= 1) {
        int tv = (t >= d) ? sh[t - d] : 0;
        __syncthreads();
        sh[t] += tv;
        __syncthreads();
    }
    if (i < N_NODES) g_off[i] = sh[t] - v;
    if (t == 1023) g_bsum[blockIdx.x] = sh[1023];
}
__global__ void k_scan2() {
    __shared__ int sh[1024];
    int t = threadIdx.x;
    int v = (t < SCAN_NB) ? g_bsum[t] : 0;
    sh[t] = v;
    __syncthreads();
    for (int d = 1; d < 1024; d <<= 1) {
        int tv = (t >= d) ? sh[t - d] : 0;
        __syncthreads();
        sh[t] += tv;
        __syncthreads();
    }
    if (t < SCAN_NB) g_bsum[t] = sh[t] - v;
}
__global__ void k_scan3() {
    int i = blockIdx.x * blockDim.x + threadIdx.x;
    if (i < N_NODES) {
        int o = g_off[i] + g_bsum[i >> 10];
        g_off[i] = o;
        g_cnt[i] = o;
    }
    if (i == 0) g_off[N_NODES] = N_EDGES;
}
__global__ void k_scatter(const int* __restrict__ src, const int* __restrict__ dst) {
    int e = blockIdx.x * blockDim.x + threadIdx.x;
    if (e < N_EDGES) {
        int d = dst[e];
        int pos = atomicAdd(&g_cnt[d], 1);
        g_ssrc[pos] = src[e];
    }
}

// ---------------- weight precompute ----------------
__global__ void k_wprep(const float* __restrict__ Wl, const float* __restrict__ Wr,
                        __nv_bfloat16* __restrict__ Bh, __nv_bfloat16* __restrict__ Bl) {
    int idx = blockIdx.x * blockDim.x + threadIdx.x;
    if (idx >= 32768) return;
    int o = idx >> 7, k = idx & 127;
    float f = (o < 128) ? Wl[o * 128 + k] : Wr[(o - 128) * 128 + k];
    __nv_bfloat16 h = __float2bfloat16(f);
    Bh[idx] = h;
    Bl[idx] = __float2bfloat16(f - __bfloat162float(h));
}

// ---------------- shared GEMM machinery ----------------
#define AROW 272
#define BROW 272
#define SB_H 1024
#define SB_L (SB_H + 256 * BROW)
#define SA_H (SB_L + 256 * BROW)
#define SA_L (SA_H + 128 * AROW)
#define SMEM_P (SA_L + 128 * AROW)

__device__ __forceinline__ uint32_t smem_u32(const void* p) {
    uint32_t a;
    asm("{ .reg .u64 t; cvta.to.shared.u64 t, %1; cvt.u32.u64 %0, t; }"
        : "=r"(a) : "l"(p));
    return a;
}
__device__ __forceinline__ uint32_t pack_bf2(__nv_bfloat16 a, __nv_bfloat16 b) {
    return (uint32_t)__bfloat16_as_ushort(a) | ((uint32_t)__bfloat16_as_ushort(b) << 16);
}
__device__ __forceinline__ void split_store(char* sm, uint32_t byte_off,
                                            float x, float y) {
    __nv_bfloat16 h0 = __float2bfloat16(x), h1 = __float2bfloat16(y);
    float r0 = x - __bfloat162float(h0), r1 = y - __bfloat162float(h1);
    __nv_bfloat16 l0 = __float2bfloat16(r0), l1 = __float2bfloat16(r1);
    *(uint32_t*)(sm + SA_H + byte_off) = pack_bf2(h0, h1);
    *(uint32_t*)(sm + SA_L + byte_off) = pack_bf2(l0, l1);
}
__device__ __forceinline__ void mma16816(float* d, const uint32_t* a,
                                         uint32_t b0, uint32_t b1) {
    asm volatile(
        "mma.sync.aligned.m16n8k16.row.col.f32.bf16.bf16.f32 "
        "{%0,%1,%2,%3}, {%4,%5,%6,%7}, {%8,%9}, {%0,%1,%2,%3};"
        : "+f"(d[0]), "+f"(d[1]), "+f"(d[2]), "+f"(d[3])
        : "r"(a[0]), "r"(a[1]), "r"(a[2]), "r"(a[3]), "r"(b0), "r"(b1));
}
#define LDSM_X4(r0, r1, r2, r3, addr)                                        \
    asm volatile("ldmatrix.sync.aligned.m8n8.x4.shared.b16 {%0,%1,%2,%3}, [%4];" \
                 : "=r"(r0), "=r"(r1), "=r"(r2), "=r"(r3) : "r"(addr))

__device__ __forceinline__ void stage_B(char* sm, const uint4* BhG, const uint4* BlG,
                                        int tid) {
    for (int idx = tid; idx < 4096; idx += 256) {
        int o = idx >> 4, c = idx & 15;
        *(uint4*)(sm + SB_H + o * BROW + c * 16) = BhG[idx];
        *(uint4*)(sm + SB_L + o * BROW + c * 16) = BlG[idx];
    }
}

// MMA + epilogue over staged A/B; writes Z/Y fp16
__device__ __forceinline__ void mma_and_epilogue(
    char* sm, uint32_t smb, int nbase, int wid, int lane,
    const float* sbias, uint4* Z, uint4* Y) {
    int g = lane >> 2;
    int t4 = lane & 3;
    int wm = wid & 3;
    int wn = wid >> 2;
    uint32_t a_off0 = (uint32_t)((wm * 32 + (lane & 15)) * AROW + ((lane >> 4) * 8) * 2);
    uint32_t a_off1 = a_off0 + 16 * AROW;
    uint32_t b_off = (uint32_t)((wn * 128 + (lane & 7) + ((lane & 16) ? 8 : 0)) * BROW +
                                ((lane & 8) ? 16 : 0));
    float acc[2][16][4];
#pragma unroll
    for (int mt = 0; mt < 2; mt++)
#pragma unroll
        for (int n8 = 0; n8 < 16; n8++)
#pragma unroll
            for (int q = 0; q < 4; q++) acc[mt][n8][q] = 0.f;

#pragma unroll
    for (int pass = 0; pass < 3; pass++) {
        uint32_t Ab = smb + ((pass == 1) ? SA_L : SA_H);
        uint32_t Bb = smb + ((pass == 2) ? SB_L : SB_H);
#pragma unroll
        for (int k16 = 0; k16 < 8; k16++) {
            uint32_t ka = (uint32_t)(k16 * 32);
            uint32_t a[2][4];
            LDSM_X4(a[0][0], a[0][1], a[0][2], a[0][3], Ab + a_off0 + ka);
            LDSM_X4(a[1][0], a[1][1], a[1][2], a[1][3], Ab + a_off1 + ka);
#pragma unroll
            for (int p = 0; p < 8; p++) {
                uint32_t b0, b1, b2, b3;
                LDSM_X4(b0, b1, b2, b3, Bb + b_off + (uint32_t)(p * 16 * BROW) + ka);
                mma16816(acc[0][2 * p], a[0], b0, b1);
                mma16816(acc[0][2 * p + 1], a[0], b2, b3);
                mma16816(acc[1][2 * p], a[1], b0, b1);
                mma16816(acc[1][2 * p + 1], a[1], b2, b3);
            }
        }
    }
    __half2* Zh = (__half2*)Z;
    __half2* Yh = (__half2*)Y;
#pragma unroll
    for (int mt = 0; mt < 2; mt++) {
        int r0 = wm * 32 + mt * 16 + g;
        int gn0 = nbase + r0;
        int gn1 = gn0 + 8;
#pragma unroll
        for (int n8 = 0; n8 < 16; n8++) {
            int col = n8 * 8 + t4 * 2;
            if (wn == 0) {
                if (gn0 < N_NODES)
                    Zh[gn0 * 64 + (col >> 1)] =
                        __floats2half2_rn(acc[mt][n8][0], acc[mt][n8][1]);
                if (gn1 < N_NODES)
                    Zh[gn1 * 64 + (col >> 1)] =
                        __floats2half2_rn(acc[mt][n8][2], acc[mt][n8][3]);
            } else {
                float b0v = sbias[col], b1v = sbias[col + 1];
                if (gn0 < N_NODES)
                    Yh[gn0 * 64 + (col >> 1)] =
                        __floats2half2_rn(acc[mt][n8][0] + b0v, acc[mt][n8][1] + b1v);
                if (gn1 < N_NODES)
                    Yh[gn1 * 64 + (col >> 1)] =
                        __floats2half2_rn(acc[mt][n8][2] + b0v, acc[mt][n8][3] + b1v);
            }
        }
    }
}

// ---------------- layer 1 projection (dense fp32 input) ----------------
__global__ void __launch_bounds__(256, 1) k_proj(
    const float* __restrict__ h, const uint4* __restrict__ BhG,
    const uint4* __restrict__ BlG, const float* __restrict__ bias,
    uint4* __restrict__ Z, uint4* __restrict__ Y) {
    extern __shared__ char sm[];
    uint32_t smb = smem_u32(sm);
    int tid = threadIdx.x;
    int wid = tid >> 5;
    int lane = tid & 31;
    float* sbias = (float*)(sm + 512);
    if (tid < HID) sbias[tid] = bias[tid];
    stage_B(sm, BhG, BlG, tid);

    for (int tile = blockIdx.x; tile < NTILES128; tile += gridDim.x) {
        int nbase = tile * 128;
        __syncthreads();
        for (int idx = tid; idx < 8192; idx += 256) {
            int row = idx >> 6, ip = idx & 63;
            int gn = nbase + row;
            float2 v = make_float2(0.f, 0.f);
            if (gn < N_NODES) v = ((const float2*)h)[gn * 64 + ip];
            split_store(sm, (uint32_t)(row * AROW + ip * 4), v.x, v.y);
        }
        __syncthreads();
        mma_and_epilogue(sm, smb, nbase, wid, lane, sbias, Z, Y);
    }
}

// ---------------- fused layer: h = relu(agg(Zin)+Yin); Zout/Yout = h@W ----------------
// Zin/Yin and Zout/Yout MUST be disjoint buffers (cross-CTA gather reads).
__global__ void __launch_bounds__(256, 1) k_fused(
    const uint4* __restrict__ Zin, const uint4* __restrict__ Yin,
    const uint4* __restrict__ BhG, const uint4* __restrict__ BlG,
    const float* __restrict__ bias,
    uint4* __restrict__ Zout, uint4* __restrict__ Yout) {
    extern __shared__ char sm[];
    uint32_t smb = smem_u32(sm);
    int tid = threadIdx.x;
    int wid = tid >> 5;
    int lane = tid & 31;
    int l16 = lane & 15;
    int half = lane >> 4;
    float* sbias = (float*)(sm + 512);
    if (tid < HID) sbias[tid] = bias[tid];
    stage_B(sm, BhG, BlG, tid);

    for (int tile = blockIdx.x; tile < NTILES128; tile += gridDim.x) {
        int nbase = tile * 128;
        __syncthreads();  // previous tile's MMA reads done before A overwrite
        // gather phase: warp wid owns rows wid*16..+15, 2 nodes at a time
#pragma unroll 1
        for (int pr = 0; pr < 8; pr++) {
            int row = wid * 16 + pr * 2 + half;
            int node = nbase + row;
            float acc[8];
#pragma unroll
            for (int q = 0; q < 8; q++) acc[q] = 0.f;
            if (node < N_NODES) {
                int s = g_off[node];
                int e = g_off[node + 1];
                int j = s;
                for (; j + 3 < e; j += 4) {
                    int s0 = __ldg(&g_ssrc[j]);
                    int s1 = __ldg(&g_ssrc[j + 1]);
                    int s2 = __ldg(&g_ssrc[j + 2]);
                    int s3 = __ldg(&g_ssrc[j + 3]);
                    uint4 v0 = Zin[s0 * 16 + l16];
                    uint4 v1 = Zin[s1 * 16 + l16];
                    uint4 v2 = Zin[s2 * 16 + l16];
                    uint4 v3 = Zin[s3 * 16 + l16];
#pragma unroll
                    for (int q = 0; q < 4; q++) {
                        uint32_t u0 = (&v0.x)[q], u1 = (&v1.x)[q];
                        uint32_t u2 = (&v2.x)[q], u3 = (&v3.x)[q];
                        float2 f0 = __half22float2(*(__half2*)&u0);
                        float2 f1 = __half22float2(*(__half2*)&u1);
                        float2 f2 = __half22float2(*(__half2*)&u2);
                        float2 f3 = __half22float2(*(__half2*)&u3);
                        acc[2 * q] += (f0.x + f1.x) + (f2.x + f3.x);
                        acc[2 * q + 1] += (f0.y + f1.y) + (f2.y + f3.y);
                    }
                }
                for (; j < e; j++) {
                    int s0 = __ldg(&g_ssrc[j]);
                    uint4 v0 = Zin[s0 * 16 + l16];
#pragma unroll
                    for (int q = 0; q < 4; q++) {
                        uint32_t u0 = (&v0.x)[q];
                        float2 f0 = __half22float2(*(__half2*)&u0);
                        acc[2 * q] += f0.x;
                        acc[2 * q + 1] += f0.y;
                    }
                }
                uint4 yv = Yin[node * 16 + l16];
#pragma unroll
                for (int q = 0; q < 4; q++) {
                    uint32_t u = (&yv.x)[q];
                    float2 f = __half22float2(*(__half2*)&u);
                    acc[2 * q] = fmaxf(acc[2 * q] + f.x, 0.f);
                    acc[2 * q + 1] = fmaxf(acc[2 * q + 1] + f.y, 0.f);
                }
            }
            // split-store h row into smem A (cols l16*8..+7)
#pragma unroll
            for (int q = 0; q < 4; q++)
                split_store(sm, (uint32_t)(row * AROW + l16 * 16 + q * 4),
                            acc[2 * q], acc[2 * q + 1]);
        }
        __syncthreads();
        mma_and_epilogue(sm, smb, nbase, wid, lane, sbias, Zout, Yout);
    }
}

// ---------------- final aggregation: h3 = agg(Z)+Y (no relu), fp16 out ----------------
__global__ void k_agg3(const uint4* __restrict__ Z, const uint4* __restrict__ Y,
                       __half2* __restrict__ out) {
    int w = (blockIdx.x * blockDim.x + threadIdx.x) >> 5;
    int lane = threadIdx.x & 31;
    int node = w * 2 + (lane >> 4);
    int l16 = lane & 15;
    if (node >= N_NODES) return;
    int s = g_off[node];
    int e = g_off[node + 1];
    float acc[8];
#pragma unroll
    for (int q = 0; q < 8; q++) acc[q] = 0.f;
    int j = s;
    for (; j + 3 < e; j += 4) {
        int s0 = __ldg(&g_ssrc[j]);
        int s1 = __ldg(&g_ssrc[j + 1]);
        int s2 = __ldg(&g_ssrc[j + 2]);
        int s3 = __ldg(&g_ssrc[j + 3]);
        uint4 v0 = Z[s0 * 16 + l16];
        uint4 v1 = Z[s1 * 16 + l16];
        uint4 v2 = Z[s2 * 16 + l16];
        uint4 v3 = Z[s3 * 16 + l16];
#pragma unroll
        for (int q = 0; q < 4; q++) {
            uint32_t u0 = (&v0.x)[q], u1 = (&v1.x)[q], u2 = (&v2.x)[q], u3 = (&v3.x)[q];
            float2 f0 = __half22float2(*(__half2*)&u0);
            float2 f1 = __half22float2(*(__half2*)&u1);
            float2 f2 = __half22float2(*(__half2*)&u2);
            float2 f3 = __half22float2(*(__half2*)&u3);
            acc[2 * q] += (f0.x + f1.x) + (f2.x + f3.x);
            acc[2 * q + 1] += (f0.y + f1.y) + (f2.y + f3.y);
        }
    }
    for (; j < e; j++) {
        int s0 = __ldg(&g_ssrc[j]);
        uint4 v0 = Z[s0 * 16 + l16];
#pragma unroll
        for (int q = 0; q < 4; q++) {
            uint32_t u0 = (&v0.x)[q];
            float2 f0 = __half22float2(*(__half2*)&u0);
            acc[2 * q] += f0.x;
            acc[2 * q + 1] += f0.y;
        }
    }
    uint4 yv = Y[node * 16 + l16];
#pragma unroll
    for (int q = 0; q < 4; q++) {
        uint32_t u = (&yv.x)[q];
        float2 f = __half22float2(*(__half2*)&u);
        out[node * 64 + l16 * 4 + q] =
            __floats2half2_rn(acc[2 * q] + f.x, acc[2 * q + 1] + f.y);
    }
}

// ---------------- pooling (fp16 input) ----------------
__global__ void k_pool(const __half* __restrict__ h, const int* __restrict__ batch) {
    int base = blockIdx.x * 32;
    int col = threadIdx.x;
    int end = base + 32;
    if (end > N_NODES) end = N_NODES;
    if (base >= N_NODES) return;
    int cur = batch[base];
    float sum = 0.f;
    for (int n = base; n < end; n++) {
        int b = batch[n];
        if (b != cur) {
            atomicAdd(&g_pool[cur * HID + col], sum);
            sum = 0.f;
            cur = b;
        }
        sum += __half2float(h[n * HID + col]);
    }
    atomicAdd(&g_pool[cur * HID + col], sum);
}

// ---------------- output head ----------------
__global__ void k_out(const float* __restrict__ Wout, const float* __restrict__ bout,
                      float* __restrict__ out) {
    int t = threadIdx.x;
    if (t < NGRAPH * NCLASS) {
        int g = t / NCLASS;
        int c = t % NCLASS;
        float s = bout[c];
#pragma unroll 4
        for (int k = 0; k < HID; k++) s += g_pool[g * HID + k] * Wout[c * HID + k];
        out[t] = s;
    }
}

// ---------------- launch ----------------
extern "C" void kernel_launch(void* const* d_in, const int* in_sizes, int n_in,
                              void* d_out, int out_size) {
    const float* x = (const float*)d_in[0];
    const int* ei = (const int*)d_in[1];
    const int* src = ei;
    const int* dst = ei + N_EDGES;
    const int* batch = (const int*)d_in[2];
    const float* W1l = (const float*)d_in[3];
    const float* b1 = (const float*)d_in[4];
    const float* W1r = (const float*)d_in[5];
    const float* W2l = (const float*)d_in[6];
    const float* b2 = (const float*)d_in[7];
    const float* W2r = (const float*)d_in[8];
    const float* W3l = (const float*)d_in[9];
    const float* b3 = (const float*)d_in[10];
    const float* W3r = (const float*)d_in[11];
    const float* Wout = (const float*)d_in[12];
    const float* bout = (const float*)d_in[13];
    float* out = (float*)d_out;

    cudaFuncSetAttribute(k_proj, cudaFuncAttributeMaxDynamicSharedMemorySize, SMEM_P);
    cudaFuncSetAttribute(k_fused, cudaFuncAttributeMaxDynamicSharedMemorySize, SMEM_P);

    uint4* d_Z1; cudaGetSymbolAddress((void**)&d_Z1, g_Z1);
    uint4* d_Y1; cudaGetSymbolAddress((void**)&d_Y1, g_Y1);
    uint4* d_Z2; cudaGetSymbolAddress((void**)&d_Z2, g_Z2);
    uint4* d_Y2; cudaGetSymbolAddress((void**)&d_Y2, g_Y2);
    __half* d_h3; cudaGetSymbolAddress((void**)&d_h3, g_h3);
    uint4* d_Bh; cudaGetSymbolAddress((void**)&d_Bh, g_Bh);
    uint4* d_Bl; cudaGetSymbolAddress((void**)&d_Bl, g_Bl);

    // CSR build + weight precompute
    k_init<<<(N_NODES + 255) / 256, 256>>>();
    k_hist<<<(N_EDGES + 255) / 256, 256>>>(dst);
    k_wprep<<<128, 256>>>(W1l, W1r, (__nv_bfloat16*)(d_Bh), (__nv_bfloat16*)(d_Bl));
    k_wprep<<<128, 256>>>(W2l, W2r, (__nv_bfloat16*)(d_Bh + 4096),
                          (__nv_bfloat16*)(d_Bl + 4096));
    k_wprep<<<128, 256>>>(W3l, W3r, (__nv_bfloat16*)(d_Bh + 8192),
                          (__nv_bfloat16*)(d_Bl + 8192));
    k_scan1<<<SCAN_NB, 1024>>>();
    k_scan2<<<1, 1024>>>();
    k_scan3<<<(N_NODES + 255) / 256, 256>>>();
    k_scatter<<<(N_EDGES + 255) / 256, 256>>>(src, dst);

    // layer 1 projection (dense x) -> ping
    k_proj<<<PROJ_GRID, 256, SMEM_P>>>(x, d_Bh, d_Bl, b1, d_Z1, d_Y1);
    // layer 2: agg1 + relu + proj2 fused  (ping -> pong)
    k_fused<<<PROJ_GRID, 256, SMEM_P>>>(d_Z1, d_Y1, d_Bh + 4096, d_Bl + 4096, b2,
                                        d_Z2, d_Y2);
    // layer 3: agg2 + relu + proj3 fused  (pong -> ping)
    k_fused<<<PROJ_GRID, 256, SMEM_P>>>(d_Z2, d_Y2, d_Bh + 8192, d_Bl + 8192, b3,
                                        d_Z1, d_Y1);
    // final aggregation (no relu) -> fp16 h3
    k_agg3<<<(N_NODES / 2 + 7) / 8, 256>>>(d_Z1, d_Y1, (__half2*)d_h3);

    // pooling + head
    k_pool<<<(N_NODES + 31) / 32, 128>>>(d_h3, batch);
    k_out<<<1, 640>>>(Wout, bout, out);
}

// round 11
// speedup vs baseline: 2.4446x; 2.4446x over previous
#include <cuda_runtime.h>
#include <cuda_fp16.h>
#include <cstdint>

#define N_NODES 100000
#define N_EDGES 1600000
#define HID 128
#define NGRAPH 64
#define NCLASS 10
#define SCAN_NB ((N_NODES + 1023) / 1024)
#define NTILES128 ((N_NODES + 127) / 128)
#define PROJ_GRID 148

// ---------------- scratch (no allocations allowed) ----------------
__device__ uint4  g_Z[N_NODES * 16];      // h@Wl^T, fp16
__device__ uint4  g_Y[N_NODES * 16];      // h@Wr^T + b, fp16
__device__ uint4  g_h[N_NODES * 16];      // layer intermediate h, fp16
__device__ uint4  g_Bh[3 * 4096];         // per-layer [Wl;Wr] fp16 hi
__device__ uint4  g_Bl[3 * 4096];         // per-layer fp16 lo
__device__ int    g_cnt[N_NODES];
__device__ int    g_off[N_NODES + 1];
__device__ int    g_ssrc[N_EDGES];
__device__ int    g_bsum[1024];
__device__ float  g_pool[NGRAPH * HID];

// ---------------- CSR build ----------------
__global__ void k_init() {
    int i = blockIdx.x * blockDim.x + threadIdx.x;
    if (i < N_NODES) g_cnt[i] = 0;
    if (i < NGRAPH * HID) g_pool[i] = 0.0f;
}
__global__ void k_hist(const int* __restrict__ dst) {
    int e = blockIdx.x * blockDim.x + threadIdx.x;
    if (e < N_EDGES) atomicAdd(&g_cnt[dst[e]], 1);
}
__global__ void k_scan1() {
    __shared__ int sh[1024];
    int t = threadIdx.x;
    int i = blockIdx.x * 1024 + t;
    int v = (i < N_NODES) ? g_cnt[i] : 0;
    sh[t] = v;
    __syncthreads();
    for (int d = 1; d < 1024; d <<= 1) {
        int tv = (t >= d) ? sh[t - d] : 0;
        __syncthreads();
        sh[t] += tv;
        __syncthreads();
    }
    if (i < N_NODES) g_off[i] = sh[t] - v;
    if (t == 1023) g_bsum[blockIdx.x] = sh[1023];
}
__global__ void k_scan2() {
    __shared__ int sh[1024];
    int t = threadIdx.x;
    int v = (t < SCAN_NB) ? g_bsum[t] : 0;
    sh[t] = v;
    __syncthreads();
    for (int d = 1; d < 1024; d <<= 1) {
        int tv = (t >= d) ? sh[t - d] : 0;
        __syncthreads();
        sh[t] += tv;
        __syncthreads();
    }
    if (t < SCAN_NB) g_bsum[t] = sh[t] - v;
}
__global__ void k_scan3() {
    int i = blockIdx.x * blockDim.x + threadIdx.x;
    if (i < N_NODES) {
        int o = g_off[i] + g_bsum[i >> 10];
        g_off[i] = o;
        g_cnt[i] = o;
    }
    if (i == 0) g_off[N_NODES] = N_EDGES;
}
__global__ void k_scatter(const int* __restrict__ src, const int* __restrict__ dst) {
    int e = blockIdx.x * blockDim.x + threadIdx.x;
    if (e < N_EDGES) {
        int d = dst[e];
        int pos = atomicAdd(&g_cnt[d], 1);
        g_ssrc[pos] = src[e];
    }
}

// ---------------- weight precompute: [Wl;Wr] -> fp16 hi/lo, [256][128] ----------------
__global__ void k_wprep(const float* __restrict__ Wl, const float* __restrict__ Wr,
                        __half* __restrict__ Bh, __half* __restrict__ Bl) {
    int idx = blockIdx.x * blockDim.x + threadIdx.x;
    if (idx >= 32768) return;
    int o = idx >> 7, k = idx & 127;
    float f = (o < 128) ? Wl[o * 128 + k] : Wr[(o - 128) * 128 + k];
    __half h = __float2half_rn(f);
    Bh[idx] = h;
    Bl[idx] = __float2half_rn(f - __half2float(h));
}

// ---------------- GEMM machinery ----------------
#define AROW 272
#define BROW 272
#define SB_H 1024
#define SB_L (SB_H + 256 * BROW)
#define SA_H (SB_L + 256 * BROW)
#define SA_L (SA_H + 128 * AROW)
#define SMEM_P (SA_L + 128 * AROW)

__device__ __forceinline__ uint32_t smem_u32(const void* p) {
    uint32_t a;
    asm("{ .reg .u64 t; cvta.to.shared.u64 t, %1; cvt.u32.u64 %0, t; }"
        : "=r"(a) : "l"(p));
    return a;
}
__device__ __forceinline__ void mma16816f(float* d, const uint32_t* a,
                                          uint32_t b0, uint32_t b1) {
    asm volatile(
        "mma.sync.aligned.m16n8k16.row.col.f32.f16.f16.f32 "
        "{%0,%1,%2,%3}, {%4,%5,%6,%7}, {%8,%9}, {%0,%1,%2,%3};"
        : "+f"(d[0]), "+f"(d[1]), "+f"(d[2]), "+f"(d[3])
        : "r"(a[0]), "r"(a[1]), "r"(a[2]), "r"(a[3]), "r"(b0), "r"(b1));
}
#define LDSM_X4(r0, r1, r2, r3, addr)                                        \
    asm volatile("ldmatrix.sync.aligned.m8n8.x4.shared.b16 {%0,%1,%2,%3}, [%4];" \
                 : "=r"(r0), "=r"(r1), "=r"(r2), "=r"(r3) : "r"(addr))

__device__ __forceinline__ void stage_B(char* sm, const uint4* BhG, const uint4* BlG,
                                        int tid) {
    for (int idx = tid; idx < 4096; idx += 256) {
        int o = idx >> 4, c = idx & 15;
        *(uint4*)(sm + SB_H + o * BROW + c * 16) = BhG[idx];
        *(uint4*)(sm + SB_L + o * BROW + c * 16) = BlG[idx];
    }
}

// NP=3: passes (Ah,Bh),(Al,Bh),(Ah,Bl)   [layer 1: A = x split hi/lo]
// NP=2: passes (A,Bh),(A,Bl)             [layers 2/3: A fp16 exact]
template <int NP>
__device__ __forceinline__ void mma_and_epilogue(
    char* sm, uint32_t smb, int nbase, int wid, int lane,
    const float* sbias, uint4* Z, uint4* Y) {
    int g = lane >> 2;
    int t4 = lane & 3;
    int wm = wid & 3;
    int wn = wid >> 2;
    uint32_t a_off0 = (uint32_t)((wm * 32 + (lane & 15)) * AROW + ((lane >> 4) * 8) * 2);
    uint32_t a_off1 = a_off0 + 16 * AROW;
    uint32_t b_off = (uint32_t)((wn * 128 + (lane & 7) + ((lane & 16) ? 8 : 0)) * BROW +
                                ((lane & 8) ? 16 : 0));
    float acc[2][16][4];
#pragma unroll
    for (int mt = 0; mt < 2; mt++)
#pragma unroll
        for (int n8 = 0; n8 < 16; n8++)
#pragma unroll
            for (int q = 0; q < 4; q++) acc[mt][n8][q] = 0.f;

#pragma unroll
    for (int pass = 0; pass < NP; pass++) {
        uint32_t Ab, Bb;
        if (NP == 3) {
            Ab = smb + ((pass == 1) ? SA_L : SA_H);
            Bb = smb + ((pass == 2) ? SB_L : SB_H);
        } else {
            Ab = smb + SA_H;
            Bb = smb + ((pass == 1) ? SB_L : SB_H);
        }
#pragma unroll
        for (int k16 = 0; k16 < 8; k16++) {
            uint32_t ka = (uint32_t)(k16 * 32);
            uint32_t a[2][4];
            LDSM_X4(a[0][0], a[0][1], a[0][2], a[0][3], Ab + a_off0 + ka);
            LDSM_X4(a[1][0], a[1][1], a[1][2], a[1][3], Ab + a_off1 + ka);
#pragma unroll
            for (int p = 0; p < 8; p++) {
                uint32_t b0, b1, b2, b3;
                LDSM_X4(b0, b1, b2, b3, Bb + b_off + (uint32_t)(p * 16 * BROW) + ka);
                mma16816f(acc[0][2 * p], a[0], b0, b1);
                mma16816f(acc[0][2 * p + 1], a[0], b2, b3);
                mma16816f(acc[1][2 * p], a[1], b0, b1);
                mma16816f(acc[1][2 * p + 1], a[1], b2, b3);
            }
        }
    }
    __half2* Zh = (__half2*)Z;
    __half2* Yh = (__half2*)Y;
#pragma unroll
    for (int mt = 0; mt < 2; mt++) {
        int r0 = wm * 32 + mt * 16 + g;
        int gn0 = nbase + r0;
        int gn1 = gn0 + 8;
#pragma unroll
        for (int n8 = 0; n8 < 16; n8++) {
            int col = n8 * 8 + t4 * 2;
            if (wn == 0) {
                if (gn0 < N_NODES)
                    Zh[gn0 * 64 + (col >> 1)] =
                        __floats2half2_rn(acc[mt][n8][0], acc[mt][n8][1]);
                if (gn1 < N_NODES)
                    Zh[gn1 * 64 + (col >> 1)] =
                        __floats2half2_rn(acc[mt][n8][2], acc[mt][n8][3]);
            } else {
                float b0v = sbias[col], b1v = sbias[col + 1];
                if (gn0 < N_NODES)
                    Yh[gn0 * 64 + (col >> 1)] =
                        __floats2half2_rn(acc[mt][n8][0] + b0v, acc[mt][n8][1] + b1v);
                if (gn1 < N_NODES)
                    Yh[gn1 * 64 + (col >> 1)] =
                        __floats2half2_rn(acc[mt][n8][2] + b0v, acc[mt][n8][3] + b1v);
            }
        }
    }
}

// ---------------- layer-1 projection: fp32 x, A split into fp16 hi/lo (3 passes) ----
__global__ void __launch_bounds__(256, 1) k_projA(
    const float* __restrict__ x, const uint4* __restrict__ BhG,
    const uint4* __restrict__ BlG, const float* __restrict__ bias,
    uint4* __restrict__ Z, uint4* __restrict__ Y) {
    extern __shared__ char sm[];
    uint32_t smb = smem_u32(sm);
    int tid = threadIdx.x;
    int wid = tid >> 5;
    int lane = tid & 31;
    float* sbias = (float*)(sm + 512);
    if (tid < HID) sbias[tid] = bias[tid];
    stage_B(sm, BhG, BlG, tid);

    for (int tile = blockIdx.x; tile < NTILES128; tile += gridDim.x) {
        int nbase = tile * 128;
        __syncthreads();
        for (int idx = tid; idx < 8192; idx += 256) {
            int row = idx >> 6, ip = idx & 63;
            int gn = nbase + row;
            float2 v = make_float2(0.f, 0.f);
            if (gn < N_NODES) v = ((const float2*)x)[gn * 64 + ip];
            __half h0 = __float2half_rn(v.x), h1 = __float2half_rn(v.y);
            __half l0 = __float2half_rn(v.x - __half2float(h0));
            __half l1 = __float2half_rn(v.y - __half2float(h1));
            uint32_t off = (uint32_t)(row * AROW + ip * 4);
            *(__half2*)(sm + SA_H + off) = __halves2half2(h0, h1);
            *(__half2*)(sm + SA_L + off) = __halves2half2(l0, l1);
        }
        __syncthreads();
        mma_and_epilogue<3>(sm, smb, nbase, wid, lane, sbias, Z, Y);
    }
}

// ---------------- layers 2/3 projection: fp16 h input (exact A, 2 passes) ----------
__global__ void __launch_bounds__(256, 1) k_projH(
    const uint4* __restrict__ h, const uint4* __restrict__ BhG,
    const uint4* __restrict__ BlG, const float* __restrict__ bias,
    uint4* __restrict__ Z, uint4* __restrict__ Y) {
    extern __shared__ char sm[];
    uint32_t smb = smem_u32(sm);
    int tid = threadIdx.x;
    int wid = tid >> 5;
    int lane = tid & 31;
    float* sbias = (float*)(sm + 512);
    if (tid < HID) sbias[tid] = bias[tid];
    stage_B(sm, BhG, BlG, tid);

    for (int tile = blockIdx.x; tile < NTILES128; tile += gridDim.x) {
        int nbase = tile * 128;
        __syncthreads();
        // A stage: straight uint4 copy of fp16 rows
        for (int idx = tid; idx < 2048; idx += 256) {
            int row = idx >> 4, c = idx & 15;
            int gn = nbase + row;
            uint4 v = make_uint4(0, 0, 0, 0);
            if (gn < N_NODES) v = h[gn * 16 + c];
            *(uint4*)(sm + SA_H + row * AROW + c * 16) = v;
        }
        __syncthreads();
        mma_and_epilogue<2>(sm, smb, nbase, wid, lane, sbias, Z, Y);
    }
}

// ---------------- aggregation: out = relu?(S@Z + Y), fp16 out, 2 nodes/warp ----------
__global__ void k_agg(const uint4* __restrict__ Z, const uint4* __restrict__ Y,
                      __half2* __restrict__ out, int do_relu) {
    int w = (blockIdx.x * blockDim.x + threadIdx.x) >> 5;
    int lane = threadIdx.x & 31;
    int node = w * 2 + (lane >> 4);
    int l16 = lane & 15;
    if (node >= N_NODES) return;
    int s = g_off[node];
    int e = g_off[node + 1];
    float acc[8];
#pragma unroll
    for (int q = 0; q < 8; q++) acc[q] = 0.f;
    int j = s;
    for (; j + 3 < e; j += 4) {
        int s0 = __ldg(&g_ssrc[j]);
        int s1 = __ldg(&g_ssrc[j + 1]);
        int s2 = __ldg(&g_ssrc[j + 2]);
        int s3 = __ldg(&g_ssrc[j + 3]);
        uint4 v0 = Z[s0 * 16 + l16];
        uint4 v1 = Z[s1 * 16 + l16];
        uint4 v2 = Z[s2 * 16 + l16];
        uint4 v3 = Z[s3 * 16 + l16];
#pragma unroll
        for (int q = 0; q < 4; q++) {
            uint32_t u0 = (&v0.x)[q], u1 = (&v1.x)[q], u2 = (&v2.x)[q], u3 = (&v3.x)[q];
            float2 f0 = __half22float2(*(__half2*)&u0);
            float2 f1 = __half22float2(*(__half2*)&u1);
            float2 f2 = __half22float2(*(__half2*)&u2);
            float2 f3 = __half22float2(*(__half2*)&u3);
            acc[2 * q] += (f0.x + f1.x) + (f2.x + f3.x);
            acc[2 * q + 1] += (f0.y + f1.y) + (f2.y + f3.y);
        }
    }
    for (; j < e; j++) {
        int s0 = __ldg(&g_ssrc[j]);
        uint4 v0 = Z[s0 * 16 + l16];
#pragma unroll
        for (int q = 0; q < 4; q++) {
            uint32_t u0 = (&v0.x)[q];
            float2 f0 = __half22float2(*(__half2*)&u0);
            acc[2 * q] += f0.x;
            acc[2 * q + 1] += f0.y;
        }
    }
    uint4 yv = Y[node * 16 + l16];
#pragma unroll
    for (int q = 0; q < 4; q++) {
        uint32_t u = (&yv.x)[q];
        float2 f = __half22float2(*(__half2*)&u);
        float rx = acc[2 * q] + f.x;
        float ry = acc[2 * q + 1] + f.y;
        if (do_relu) { rx = fmaxf(rx, 0.f); ry = fmaxf(ry, 0.f); }
        out[node * 64 + l16 * 4 + q] = __floats2half2_rn(rx, ry);
    }
}

// ---------------- pooling (fp16 input) ----------------
__global__ void k_pool(const __half* __restrict__ h, const int* __restrict__ batch) {
    int base = blockIdx.x * 32;
    int col = threadIdx.x;
    int end = base + 32;
    if (end > N_NODES) end = N_NODES;
    if (base >= N_NODES) return;
    int cur = batch[base];
    float sum = 0.f;
    for (int n = base; n < end; n++) {
        int b = batch[n];
        if (b != cur) {
            atomicAdd(&g_pool[cur * HID + col], sum);
            sum = 0.f;
            cur = b;
        }
        sum += __half2float(h[n * HID + col]);
    }
    atomicAdd(&g_pool[cur * HID + col], sum);
}

// ---------------- output head ----------------
__global__ void k_out(const float* __restrict__ Wout, const float* __restrict__ bout,
                      float* __restrict__ out) {
    int t = threadIdx.x;
    if (t < NGRAPH * NCLASS) {
        int g = t / NCLASS;
        int c = t % NCLASS;
        float s = bout[c];
#pragma unroll 4
        for (int k = 0; k < HID; k++) s += g_pool[g * HID + k] * Wout[c * HID + k];
        out[t] = s;
    }
}

// ---------------- launch ----------------
extern "C" void kernel_launch(void* const* d_in, const int* in_sizes, int n_in,
                              void* d_out, int out_size) {
    const float* x = (const float*)d_in[0];
    const int* ei = (const int*)d_in[1];
    const int* src = ei;
    const int* dst = ei + N_EDGES;
    const int* batch = (const int*)d_in[2];
    const float* W1l = (const float*)d_in[3];
    const float* b1 = (const float*)d_in[4];
    const float* W1r = (const float*)d_in[5];
    const float* W2l = (const float*)d_in[6];
    const float* b2 = (const float*)d_in[7];
    const float* W2r = (const float*)d_in[8];
    const float* W3l = (const float*)d_in[9];
    const float* b3 = (const float*)d_in[10];
    const float* W3r = (const float*)d_in[11];
    const float* Wout = (const float*)d_in[12];
    const float* bout = (const float*)d_in[13];
    float* out = (float*)d_out;

    cudaFuncSetAttribute(k_projA, cudaFuncAttributeMaxDynamicSharedMemorySize, SMEM_P);
    cudaFuncSetAttribute(k_projH, cudaFuncAttributeMaxDynamicSharedMemorySize, SMEM_P);

    uint4* d_Z; cudaGetSymbolAddress((void**)&d_Z, g_Z);
    uint4* d_Y; cudaGetSymbolAddress((void**)&d_Y, g_Y);
    uint4* d_h; cudaGetSymbolAddress((void**)&d_h, g_h);
    uint4* d_Bh; cudaGetSymbolAddress((void**)&d_Bh, g_Bh);
    uint4* d_Bl; cudaGetSymbolAddress((void**)&d_Bl, g_Bl);

    // CSR build + weight precompute
    k_init<<<(N_NODES + 255) / 256, 256>>>();
    k_hist<<<(N_EDGES + 255) / 256, 256>>>(dst);
    k_wprep<<<128, 256>>>(W1l, W1r, (__half*)(d_Bh), (__half*)(d_Bl));
    k_wprep<<<128, 256>>>(W2l, W2r, (__half*)(d_Bh + 4096), (__half*)(d_Bl + 4096));
    k_wprep<<<128, 256>>>(W3l, W3r, (__half*)(d_Bh + 8192), (__half*)(d_Bl + 8192));
    k_scan1<<<SCAN_NB, 1024>>>();
    k_scan2<<<1, 1024>>>();
    k_scan3<<<(N_NODES + 255) / 256, 256>>>();
    k_scatter<<<(N_EDGES + 255) / 256, 256>>>(src, dst);

    // layer 1: x -> Z,Y -> h (relu)
    k_projA<<<PROJ_GRID, 256, SMEM_P>>>(x, d_Bh, d_Bl, b1, d_Z, d_Y);
    k_agg<<<(N_NODES / 2 + 7) / 8, 256>>>(d_Z, d_Y, (__half2*)d_h, 1);
    // layer 2
    k_projH<<<PROJ_GRID, 256, SMEM_P>>>(d_h, d_Bh + 4096, d_Bl + 4096, b2, d_Z, d_Y);
    k_agg<<<(N_NODES / 2 + 7) / 8, 256>>>(d_Z, d_Y, (__half2*)d_h, 1);
    // layer 3 (no relu)
    k_projH<<<PROJ_GRID, 256, SMEM_P>>>(d_h, d_Bh + 8192, d_Bl + 8192, b3, d_Z, d_Y);
    k_agg<<<(N_NODES / 2 + 7) / 8, 256>>>(d_Z, d_Y, (__half2*)d_h, 0);

    // pooling + head
    k_pool<<<(N_NODES + 31) / 32, 128>>>((const __half*)d_h, batch);
    k_out<<<1, 640>>>(Wout, bout, out);
}

// round 13
// speedup vs baseline: 2.5553x; 1.0453x over previous
#include <cuda_runtime.h>
#include <cuda_fp16.h>
#include <cstdint>

#define N_NODES 100000
#define N_EDGES 1600000
#define HID 128
#define NGRAPH 64
#define NCLASS 10
#define SCAN_NB ((N_NODES + 1023) / 1024)
#define NTILES128 ((N_NODES + 127) / 128)
#define PROJ_GRID 148

// ---------------- scratch (no allocations allowed) ----------------
__device__ uint4  g_Z[N_NODES * 16];      // h@Wl^T, fp16
__device__ uint4  g_Y[N_NODES * 16];      // h@Wr^T + b, fp16
__device__ uint4  g_h[N_NODES * 16];      // layer intermediate h, fp16
__device__ uint4  g_Bh[3 * 4096];         // per-layer [Wl;Wr] fp16 hi
__device__ uint4  g_Bl[3 * 4096];         // per-layer fp16 lo
__device__ int    g_cnt[N_NODES];
__device__ int    g_off[N_NODES + 1];
__device__ int    g_ssrc[N_EDGES];
__device__ int    g_bsum[1024];
__device__ float  g_pool[NGRAPH * HID];

// ---------------- CSR build ----------------
__global__ void k_init() {
    int i = blockIdx.x * blockDim.x + threadIdx.x;
    if (i < N_NODES) g_cnt[i] = 0;
    if (i < NGRAPH * HID) g_pool[i] = 0.0f;
}
__global__ void k_hist(const int* __restrict__ dst) {
    int e = blockIdx.x * blockDim.x + threadIdx.x;
    if (e < N_EDGES) atomicAdd(&g_cnt[dst[e]], 1);
}
__global__ void k_scan1() {
    __shared__ int sh[1024];
    int t = threadIdx.x;
    int i = blockIdx.x * 1024 + t;
    int v = (i < N_NODES) ? g_cnt[i] : 0;
    sh[t] = v;
    __syncthreads();
    for (int d = 1; d < 1024; d <<= 1) {
        int tv = (t >= d) ? sh[t - d] : 0;
        __syncthreads();
        sh[t] += tv;
        __syncthreads();
    }
    if (i < N_NODES) g_off[i] = sh[t] - v;
    if (t == 1023) g_bsum[blockIdx.x] = sh[1023];
}
__global__ void k_scan2() {
    __shared__ int sh[1024];
    int t = threadIdx.x;
    int v = (t < SCAN_NB) ? g_bsum[t] : 0;
    sh[t] = v;
    __syncthreads();
    for (int d = 1; d < 1024; d <<= 1) {
        int tv = (t >= d) ? sh[t - d] : 0;
        __syncthreads();
        sh[t] += tv;
        __syncthreads();
    }
    if (t < SCAN_NB) g_bsum[t] = sh[t] - v;
}
__global__ void k_scan3() {
    int i = blockIdx.x * blockDim.x + threadIdx.x;
    if (i < N_NODES) {
        int o = g_off[i] + g_bsum[i >> 10];
        g_off[i] = o;
        g_cnt[i] = o;
    }
    if (i == 0) g_off[N_NODES] = N_EDGES;
}
__global__ void k_scatter(const int* __restrict__ src, const int* __restrict__ dst) {
    int e = blockIdx.x * blockDim.x + threadIdx.x;
    if (e < N_EDGES) {
        int d = dst[e];
        int pos = atomicAdd(&g_cnt[d], 1);
        g_ssrc[pos] = src[e];
    }
}

// ---------------- all-layer weight precompute: [Wl;Wr] -> fp16 hi/lo ----------------
__global__ void k_wprep_all(const float* __restrict__ W1l, const float* __restrict__ W1r,
                            const float* __restrict__ W2l, const float* __restrict__ W2r,
                            const float* __restrict__ W3l, const float* __restrict__ W3r,
                            __half* __restrict__ Bh, __half* __restrict__ Bl) {
    int idx = blockIdx.x * blockDim.x + threadIdx.x;
    if (idx >= 3 * 32768) return;
    int layer = idx >> 15;
    int r = idx & 32767;
    int o = r >> 7, k = r & 127;
    const float* W = (layer == 0) ? ((o < 128) ? W1l : W1r)
                   : (layer == 1) ? ((o < 128) ? W2l : W2r)
                                  : ((o < 128) ? W3l : W3r);
    float f = W[(o & 127) * 128 + k];
    __half h = __float2half_rn(f);
    Bh[idx] = h;
    Bl[idx] = __float2half_rn(f - __half2float(h));
}

// ---------------- GEMM machinery ----------------
#define AROW 272
#define BROW 272
#define SB_H 1024
#define SB_L (SB_H + 256 * BROW)
#define SA_H (SB_L + 256 * BROW)
#define SA_L (SA_H + 128 * AROW)
#define SMEM_P (SA_L + 128 * AROW)

__device__ __forceinline__ uint32_t smem_u32(const void* p) {
    uint32_t a;
    asm("{ .reg .u64 t; cvta.to.shared.u64 t, %1; cvt.u32.u64 %0, t; }"
        : "=r"(a) : "l"(p));
    return a;
}
__device__ __forceinline__ void mma16816f(float* d, const uint32_t* a,
                                          uint32_t b0, uint32_t b1) {
    asm volatile(
        "mma.sync.aligned.m16n8k16.row.col.f32.f16.f16.f32 "
        "{%0,%1,%2,%3}, {%4,%5,%6,%7}, {%8,%9}, {%0,%1,%2,%3};"
        : "+f"(d[0]), "+f"(d[1]), "+f"(d[2]), "+f"(d[3])
        : "r"(a[0]), "r"(a[1]), "r"(a[2]), "r"(a[3]), "r"(b0), "r"(b1));
}
#define LDSM_X4(r0, r1, r2, r3, addr)                                        \
    asm volatile("ldmatrix.sync.aligned.m8n8.x4.shared.b16 {%0,%1,%2,%3}, [%4];" \
                 : "=r"(r0), "=r"(r1), "=r"(r2), "=r"(r3) : "r"(addr))

__device__ __forceinline__ void stage_B(char* sm, const uint4* BhG, const uint4* BlG,
                                        int tid) {
    for (int idx = tid; idx < 4096; idx += 256) {
        int o = idx >> 4, c = idx & 15;
        *(uint4*)(sm + SB_H + o * BROW + c * 16) = BhG[idx];
        *(uint4*)(sm + SB_L + o * BROW + c * 16) = BlG[idx];
    }
}

// NP=3: acc = Ah*(Bh+Bl) + Al*Bh   [layer 1: A = x split hi/lo]
// NP=2: acc = A*(Bh+Bl)            [layers 2/3: A fp16 exact]
// A fragments loaded ONCE per k16 and reused for both B passes.
template <int NP>
__device__ __forceinline__ void mma_and_epilogue(
    char* sm, uint32_t smb, int nbase, int wid, int lane,
    const float* sbias, uint4* Z, uint4* Y) {
    int g = lane >> 2;
    int t4 = lane & 3;
    int wm = wid & 3;
    int wn = wid >> 2;
    uint32_t a_off0 = (uint32_t)((wm * 32 + (lane & 15)) * AROW + ((lane >> 4) * 8) * 2);
    uint32_t a_off1 = a_off0 + 16 * AROW;
    uint32_t b_off = (uint32_t)((wn * 128 + (lane & 7) + ((lane & 16) ? 8 : 0)) * BROW +
                                ((lane & 8) ? 16 : 0));
    float acc[2][16][4];
#pragma unroll
    for (int mt = 0; mt < 2; mt++)
#pragma unroll
        for (int n8 = 0; n8 < 16; n8++)
#pragma unroll
            for (int q = 0; q < 4; q++) acc[mt][n8][q] = 0.f;

#pragma unroll
    for (int k16 = 0; k16 < 8; k16++) {
        uint32_t ka = (uint32_t)(k16 * 32);
        uint32_t ah[2][4], al[2][4];
        LDSM_X4(ah[0][0], ah[0][1], ah[0][2], ah[0][3], smb + SA_H + a_off0 + ka);
        LDSM_X4(ah[1][0], ah[1][1], ah[1][2], ah[1][3], smb + SA_H + a_off1 + ka);
        if (NP == 3) {
            LDSM_X4(al[0][0], al[0][1], al[0][2], al[0][3], smb + SA_L + a_off0 + ka);
            LDSM_X4(al[1][0], al[1][1], al[1][2], al[1][3], smb + SA_L + a_off1 + ka);
        }
#pragma unroll
        for (int p = 0; p < 8; p++) {
            uint32_t b0, b1, b2, b3;
            uint32_t bpo = b_off + (uint32_t)(p * 16 * BROW) + ka;
            LDSM_X4(b0, b1, b2, b3, smb + SB_H + bpo);
            mma16816f(acc[0][2 * p], ah[0], b0, b1);
            mma16816f(acc[0][2 * p + 1], ah[0], b2, b3);
            mma16816f(acc[1][2 * p], ah[1], b0, b1);
            mma16816f(acc[1][2 * p + 1], ah[1], b2, b3);
            if (NP == 3) {
                mma16816f(acc[0][2 * p], al[0], b0, b1);
                mma16816f(acc[0][2 * p + 1], al[0], b2, b3);
                mma16816f(acc[1][2 * p], al[1], b0, b1);
                mma16816f(acc[1][2 * p + 1], al[1], b2, b3);
            }
            LDSM_X4(b0, b1, b2, b3, smb + SB_L + bpo);
            mma16816f(acc[0][2 * p], ah[0], b0, b1);
            mma16816f(acc[0][2 * p + 1], ah[0], b2, b3);
            mma16816f(acc[1][2 * p], ah[1], b0, b1);
            mma16816f(acc[1][2 * p + 1], ah[1], b2, b3);
        }
    }

    __half2* Zh = (__half2*)Z;
    __half2* Yh = (__half2*)Y;
#pragma unroll
    for (int mt = 0; mt < 2; mt++) {
        int r0 = wm * 32 + mt * 16 + g;
        int gn0 = nbase + r0;
        int gn1 = gn0 + 8;
#pragma unroll
        for (int n8 = 0; n8 < 16; n8++) {
            int col = n8 * 8 + t4 * 2;
            if (wn == 0) {
                if (gn0 < N_NODES)
                    Zh[gn0 * 64 + (col >> 1)] =
                        __floats2half2_rn(acc[mt][n8][0], acc[mt][n8][1]);
                if (gn1 < N_NODES)
                    Zh[gn1 * 64 + (col >> 1)] =
                        __floats2half2_rn(acc[mt][n8][2], acc[mt][n8][3]);
            } else {
                float b0v = sbias[col], b1v = sbias[col + 1];
                if (gn0 < N_NODES)
                    Yh[gn0 * 64 + (col >> 1)] =
                        __floats2half2_rn(acc[mt][n8][0] + b0v, acc[mt][n8][1] + b1v);
                if (gn1 < N_NODES)
                    Yh[gn1 * 64 + (col >> 1)] =
                        __floats2half2_rn(acc[mt][n8][2] + b0v, acc[mt][n8][3] + b1v);
            }
        }
    }
}

// ---------------- layer-1 projection: fp32 x, A split fp16 hi/lo (3 passes) ----------
__global__ void __launch_bounds__(256, 1) k_projA(
    const float* __restrict__ x, const uint4* __restrict__ BhG,
    const uint4* __restrict__ BlG, const float* __restrict__ bias,
    uint4* __restrict__ Z, uint4* __restrict__ Y) {
    extern __shared__ char sm[];
    uint32_t smb = smem_u32(sm);
    int tid = threadIdx.x;
    int wid = tid >> 5;
    int lane = tid & 31;
    float* sbias = (float*)(sm + 512);
    if (tid < HID) sbias[tid] = bias[tid];
    stage_B(sm, BhG, BlG, tid);

    for (int tile = blockIdx.x; tile < NTILES128; tile += gridDim.x) {
        int nbase = tile * 128;
        __syncthreads();
        for (int idx = tid; idx < 8192; idx += 256) {
            int row = idx >> 6, ip = idx & 63;
            int gn = nbase + row;
            float2 v = make_float2(0.f, 0.f);
            if (gn < N_NODES) v = ((const float2*)x)[gn * 64 + ip];
            __half h0 = __float2half_rn(v.x), h1 = __float2half_rn(v.y);
            __half l0 = __float2half_rn(v.x - __half2float(h0));
            __half l1 = __float2half_rn(v.y - __half2float(h1));
            uint32_t off = (uint32_t)(row * AROW + ip * 4);
            *(__half2*)(sm + SA_H + off) = __halves2half2(h0, h1);
            *(__half2*)(sm + SA_L + off) = __halves2half2(l0, l1);
        }
        __syncthreads();
        mma_and_epilogue<3>(sm, smb, nbase, wid, lane, sbias, Z, Y);
    }
}

// ---------------- layers 2/3 projection: fp16 h input (exact A, 2 passes) ----------
__global__ void __launch_bounds__(256, 1) k_projH(
    const uint4* __restrict__ h, const uint4* __restrict__ BhG,
    const uint4* __restrict__ BlG, const float* __restrict__ bias,
    uint4* __restrict__ Z, uint4* __restrict__ Y) {
    extern __shared__ char sm[];
    uint32_t smb = smem_u32(sm);
    int tid = threadIdx.x;
    int wid = tid >> 5;
    int lane = tid & 31;
    float* sbias = (float*)(sm + 512);
    if (tid < HID) sbias[tid] = bias[tid];
    stage_B(sm, BhG, BlG, tid);

    for (int tile = blockIdx.x; tile < NTILES128; tile += gridDim.x) {
        int nbase = tile * 128;
        __syncthreads();
        for (int idx = tid; idx < 2048; idx += 256) {
            int row = idx >> 4, c = idx & 15;
            int gn = nbase + row;
            uint4 v = make_uint4(0, 0, 0, 0);
            if (gn < N_NODES) v = h[gn * 16 + c];
            *(uint4*)(sm + SA_H + row * AROW + c * 16) = v;
        }
        __syncthreads();
        mma_and_epilogue<2>(sm, smb, nbase, wid, lane, sbias, Z, Y);
    }
}

// ---------------- aggregation: out = relu?(S@Z + Y), fp16 out, 2 nodes/warp ----------
__global__ void k_agg(const uint4* __restrict__ Z, const uint4* __restrict__ Y,
                      __half2* __restrict__ out, int do_relu) {
    int w = (blockIdx.x * blockDim.x + threadIdx.x) >> 5;
    int lane = threadIdx.x & 31;
    int node = w * 2 + (lane >> 4);
    int l16 = lane & 15;
    if (node >= N_NODES) return;
    int s = g_off[node];
    int e = g_off[node + 1];
    float acc[8];
#pragma unroll
    for (int q = 0; q < 8; q++) acc[q] = 0.f;
    int j = s;
    for (; j + 3 < e; j += 4) {
        int s0 = __ldg(&g_ssrc[j]);
        int s1 = __ldg(&g_ssrc[j + 1]);
        int s2 = __ldg(&g_ssrc[j + 2]);
        int s3 = __ldg(&g_ssrc[j + 3]);
        uint4 v0 = Z[s0 * 16 + l16];
        uint4 v1 = Z[s1 * 16 + l16];
        uint4 v2 = Z[s2 * 16 + l16];
        uint4 v3 = Z[s3 * 16 + l16];
#pragma unroll
        for (int q = 0; q < 4; q++) {
            uint32_t u0 = (&v0.x)[q], u1 = (&v1.x)[q], u2 = (&v2.x)[q], u3 = (&v3.x)[q];
            float2 f0 = __half22float2(*(__half2*)&u0);
            float2 f1 = __half22float2(*(__half2*)&u1);
            float2 f2 = __half22float2(*(__half2*)&u2);
            float2 f3 = __half22float2(*(__half2*)&u3);
            acc[2 * q] += (f0.x + f1.x) + (f2.x + f3.x);
            acc[2 * q + 1] += (f0.y + f1.y) + (f2.y + f3.y);
        }
    }
    for (; j < e; j++) {
        int s0 = __ldg(&g_ssrc[j]);
        uint4 v0 = Z[s0 * 16 + l16];
#pragma unroll
        for (int q = 0; q < 4; q++) {
            uint32_t u0 = (&v0.x)[q];
            float2 f0 = __half22float2(*(__half2*)&u0);
            acc[2 * q] += f0.x;
            acc[2 * q + 1] += f0.y;
        }
    }
    uint4 yv = Y[node * 16 + l16];
#pragma unroll
    for (int q = 0; q < 4; q++) {
        uint32_t u = (&yv.x)[q];
        float2 f = __half22float2(*(__half2*)&u);
        float rx = acc[2 * q] + f.x;
        float ry = acc[2 * q + 1] + f.y;
        if (do_relu) { rx = fmaxf(rx, 0.f); ry = fmaxf(ry, 0.f); }
        out[node * 64 + l16 * 4 + q] = __floats2half2_rn(rx, ry);
    }
}

// ---------------- pooling (fp16 input) ----------------
__global__ void k_pool(const __half* __restrict__ h, const int* __restrict__ batch) {
    int base = blockIdx.x * 32;
    int col = threadIdx.x;
    int end = base + 32;
    if (end > N_NODES) end = N_NODES;
    if (base >= N_NODES) return;
    int cur = batch[base];
    float sum = 0.f;
    for (int n = base; n < end; n++) {
        int b = batch[n];
        if (b != cur) {
            atomicAdd(&g_pool[cur * HID + col], sum);
            sum = 0.f;
            cur = b;
        }
        sum += __half2float(h[n * HID + col]);
    }
    atomicAdd(&g_pool[cur * HID + col], sum);
}

// ---------------- output head ----------------
__global__ void k_out(const float* __restrict__ Wout, const float* __restrict__ bout,
                      float* __restrict__ out) {
    int t = threadIdx.x;
    if (t < NGRAPH * NCLASS) {
        int g = t / NCLASS;
        int c = t % NCLASS;
        float s = bout[c];
#pragma unroll 4
        for (int k = 0; k < HID; k++) s += g_pool[g * HID + k] * Wout[c * HID + k];
        out[t] = s;
    }
}

// ---------------- launch ----------------
extern "C" void kernel_launch(void* const* d_in, const int* in_sizes, int n_in,
                              void* d_out, int out_size) {
    const float* x = (const float*)d_in[0];
    const int* ei = (const int*)d_in[1];
    const int* src = ei;
    const int* dst = ei + N_EDGES;
    const int* batch = (const int*)d_in[2];
    const float* W1l = (const float*)d_in[3];
    const float* b1 = (const float*)d_in[4];
    const float* W1r = (const float*)d_in[5];
    const float* W2l = (const float*)d_in[6];
    const float* b2 = (const float*)d_in[7];
    const float* W2r = (const float*)d_in[8];
    const float* W3l = (const float*)d_in[9];
    const float* b3 = (const float*)d_in[10];
    const float* W3r = (const float*)d_in[11];
    const float* Wout = (const float*)d_in[12];
    const float* bout = (const float*)d_in[13];
    float* out = (float*)d_out;

    cudaFuncSetAttribute(k_projA, cudaFuncAttributeMaxDynamicSharedMemorySize, SMEM_P);
    cudaFuncSetAttribute(k_projH, cudaFuncAttributeMaxDynamicSharedMemorySize, SMEM_P);

    uint4* d_Z; cudaGetSymbolAddress((void**)&d_Z, g_Z);
    uint4* d_Y; cudaGetSymbolAddress((void**)&d_Y, g_Y);
    uint4* d_h; cudaGetSymbolAddress((void**)&d_h, g_h);
    uint4* d_Bh; cudaGetSymbolAddress((void**)&d_Bh, g_Bh);
    uint4* d_Bl; cudaGetSymbolAddress((void**)&d_Bl, g_Bl);

    // CSR build + weight precompute (single stream, no forking)
    k_init<<<(N_NODES + 255) / 256, 256>>>();
    k_hist<<<(N_EDGES + 255) / 256, 256>>>(dst);
    k_wprep_all<<<384, 256>>>(W1l, W1r, W2l, W2r, W3l, W3r,
                              (__half*)d_Bh, (__half*)d_Bl);
    k_scan1<<<SCAN_NB, 1024>>>();
    k_scan2<<<1, 1024>>>();
    k_scan3<<<(N_NODES + 255) / 256, 256>>>();
    k_scatter<<<(N_EDGES + 255) / 256, 256>>>(src, dst);

    // layer 1: x -> Z,Y -> h (relu)
    k_projA<<<PROJ_GRID, 256, SMEM_P>>>(x, d_Bh, d_Bl, b1, d_Z, d_Y);
    k_agg<<<(N_NODES / 2 + 7) / 8, 256>>>(d_Z, d_Y, (__half2*)d_h, 1);
    // layer 2
    k_projH<<<PROJ_GRID, 256, SMEM_P>>>(d_h, d_Bh + 4096, d_Bl + 4096, b2, d_Z, d_Y);
    k_agg<<<(N_NODES / 2 + 7) / 8, 256>>>(d_Z, d_Y, (__half2*)d_h, 1);
    // layer 3 (no relu)
    k_projH<<<PROJ_GRID, 256, SMEM_P>>>(d_h, d_Bh + 8192, d_Bl + 8192, b3, d_Z, d_Y);
    k_agg<<<(N_NODES / 2 + 7) / 8, 256>>>(d_Z, d_Y, (__half2*)d_h, 0);

    // pooling + head
    k_pool<<<(N_NODES + 31) / 32, 128>>>((const __half*)d_h, batch);
    k_out<<<1, 640>>>(Wout, bout, out);
}